// round 10
// baseline (speedup 1.0000x reference)
#include <cuda_runtime.h>
#include <cuda_fp16.h>
#include <math.h>
#include <stdint.h>

#define INPUT_DIM 512
#define PROJ_DIM  8192
#define HW        196
#define BATCH     32
#define NPAIRS    (INPUT_DIM * INPUT_DIM)
#define KPAD      448      // 2*196 = 392 padded to 7*64 (interleaved hi/lo fp16 splits)
#define KCHUNK    64
#define NCHUNKS   (KPAD / KCHUNK)
#define CAP       128      // bucket capacity (mean 32, Poisson tail ~0 at 128)

// ---------------- scratch (device globals; no allocation allowed) -----------
__device__ float          g_G[BATCH * INPUT_DIM * INPUT_DIM];  // Gram, batch-major (upper 128-tiles valid)
__device__ float          g_T[INPUT_DIM * INPUT_DIM * BATCH];  // Gram, batch-last
__device__ float          g_Y[PROJ_DIM * BATCH];               // pooled sketch, [bin][batch]
__device__ unsigned short g_xsp[BATCH * INPUT_DIM * KPAD];     // fp16 split-stacked x^T
__device__ int   g_h1[INPUT_DIM], g_h2[INPUT_DIM];
__device__ float g_s1[INPUT_DIM], g_s2[INPUT_DIM];
__device__ int   g_cnt[PROJ_DIM];                              // per-bin pair count
__device__ int2  g_pairs[PROJ_DIM * CAP];                      // {T-address, scale bits}
__device__ float g_norm[BATCH];                                // sum |Y| per batch

// ---------------- kernel 1: extract both count-sketches ----------------------
__global__ void extract_both_kernel(const float* __restrict__ M1,
                                    const float* __restrict__ M2) {
    int blk = blockIdx.x;
    const float* M; int* h; float* s; int row;
    if (blk < INPUT_DIM) { M = M1; h = g_h1; s = g_s1; row = blk; }
    else                 { M = M2; h = g_h2; s = g_s2; row = blk - INPUT_DIM; }
    const float* r = M + (size_t)row * PROJ_DIM;
    for (int j = threadIdx.x; j < PROJ_DIM; j += blockDim.x) {
        float v = r[j];
        if (v != 0.0f) { h[row] = j; s[row] = v; }
    }
}

// ---------------- kernel 2: fill buckets (single pass, no scan) ---------------
__global__ void fill_kernel() {
    int t = blockIdx.x * 256 + threadIdx.x;
    int c1  = t >> 7;
    int c2b = (t & 127) * 4;
    int   h1 = g_h1[c1];
    float s1 = g_s1[c1];
#pragma unroll
    for (int i = 0; i < 4; i++) {
        int c2 = c2b + i;
        int k = (h1 + g_h2[c2]) & (PROJ_DIM - 1);
        int pos = atomicAdd(&g_cnt[k], 1);
        if (pos < CAP) {
            int cmin = min(c1, c2), cmax = max(c1, c2);
            g_pairs[k * CAP + pos] =
                make_int2((cmin * INPUT_DIM + cmax) * BATCH,
                          __float_as_int(s1 * g_s2[c2]));
        }
    }
}

// ---------------- kernel 3: prep — fp16 split + transpose to [b][c][kk] -------
__global__ void prep_split_kernel(const float* __restrict__ x) {
    __shared__ float sm[64][65];
    int b = blockIdx.z, hwt = blockIdx.y, ct = blockIdx.x;
    int hw0 = hwt * 64, c0 = ct * 64;
    int t = threadIdx.x;

#pragma unroll
    for (int p = 0; p < 4; p++) {
        int row = p * 16 + (t >> 4);
        int col = (t & 15) * 4;
        int hw = hw0 + row;
        float4 v = make_float4(0.f, 0.f, 0.f, 0.f);
        if (hw < HW)
            v = *(const float4*)(x + ((size_t)(b * HW + hw)) * INPUT_DIM + c0 + col);
        sm[row][col] = v.x; sm[row][col + 1] = v.y;
        sm[row][col + 2] = v.z; sm[row][col + 3] = v.w;
    }
    __syncthreads();

    int c_i = t >> 2, q = t & 3;
    int kkbase = 2 * hw0 + q * 32;     // 32 kk = 16 hw
    if (kkbase < KPAD) {
        uint32_t outw[16];
#pragma unroll
        for (int i = 0; i < 16; i++) {
            int hwl = q * 16 + i;
            float v = (hw0 + hwl < HW) ? sm[hwl][c_i] : 0.0f;
            __half h1 = __float2half_rn(v);
            float r = v - __half2float(h1);
            __half h2 = __float2half_rn(r);
            outw[i] = ((uint32_t)__half_as_ushort(h2) << 16) |
                      (uint32_t)__half_as_ushort(h1);
        }
        uint4* dst = (uint4*)(g_xsp + ((size_t)(b * INPUT_DIM + c0 + c_i)) * KPAD + kkbase);
        const uint4* s = (const uint4*)outw;
        dst[0] = s[0]; dst[1] = s[1]; dst[2] = s[2]; dst[3] = s[3];
    }
}

// ---------------- kernel 4: HMMA fp16 Gram, ldmatrix + cp.async, occ-3 --------
#define SPITCH     72                     // fp16 elems per smem row (conflict-free)
#define TILE_ELEM  (128 * SPITCH)
#define TILE_BYTES (TILE_ELEM * 2)
#define BUF_ELEM   (2 * TILE_ELEM)        // A + B per buffer
#define BUF_BYTES  (BUF_ELEM * 2)

__device__ __forceinline__ void cp16(uint32_t dst, const void* src) {
    asm volatile("cp.async.cg.shared.global [%0], [%1], 16;" :: "r"(dst), "l"(src));
}
__device__ __forceinline__ void ldsm4(uint32_t* r, uint32_t a) {
    asm volatile("ldmatrix.sync.aligned.m8n8.x4.shared.b16 {%0,%1,%2,%3}, [%4];"
                 : "=r"(r[0]), "=r"(r[1]), "=r"(r[2]), "=r"(r[3]) : "r"(a));
}

__global__ __launch_bounds__(256, 3) void gram_hmma_kernel() {
    extern __shared__ __align__(16) unsigned short smh[];
    uint32_t smemBase = (uint32_t)__cvta_generic_to_shared(smh);

    int b = blockIdx.y;
    int tt = blockIdx.x, tm = 0, rem = 4;
    while (tt >= rem) { tt -= rem; tm++; rem--; }
    int tn = tm + tt;
    bool diag = (tm == tn);

    int t = threadIdx.x, lane = t & 31, wid = t >> 5;
    int warp_m = wid & 1, warp_n = wid >> 1;

    float acc[4][4][4];
#pragma unroll
    for (int mi = 0; mi < 4; mi++)
#pragma unroll
        for (int ni = 0; ni < 4; ni++)
#pragma unroll
            for (int j = 0; j < 4; j++) acc[mi][ni][j] = 0.0f;

    const unsigned short* baseA = g_xsp + ((size_t)(b * INPUT_DIM + tm * 128)) * KPAD;
    const unsigned short* baseB = g_xsp + ((size_t)(b * INPUT_DIM + tn * 128)) * KPAD;

    // precomputed cp.async lane geometry
    int cprow = t >> 3, cpj = (t & 7) * 8;
    uint32_t cpDst = smemBase + (uint32_t)(cprow * SPITCH + cpj) * 2;
    const unsigned short* cpSrcA = baseA + (size_t)cprow * KPAD + cpj;
    const unsigned short* cpSrcB = baseB + (size_t)cprow * KPAD + cpj;

    // precomputed ldmatrix base addresses (bytes)
    int arow = (lane & 7) + ((lane >> 3) & 1) * 8;
    int acol = (lane >> 4) * 8;
    int brow = (lane & 7) + (lane >> 4) * 8;
    int bcol = ((lane >> 3) & 1) * 8;
    uint32_t aBase = smemBase + (uint32_t)((warp_m * 64 + arow) * SPITCH + acol) * 2;
    uint32_t bBase = smemBase + (uint32_t)((warp_n * 32 + brow) * SPITCH + bcol) * 2
                     + (diag ? 0u : (uint32_t)TILE_BYTES);

    auto load_chunk = [&](int buf, int ch) {
        uint32_t d = cpDst + (uint32_t)buf * BUF_BYTES;
        const unsigned short* sA = cpSrcA + ch * KCHUNK;
#pragma unroll
        for (int i = 0; i < 4; i++)
            cp16(d + (uint32_t)(i * 32 * SPITCH * 2), sA + (size_t)(i * 32) * KPAD);
        if (!diag) {
            const unsigned short* sB = cpSrcB + ch * KCHUNK;
#pragma unroll
            for (int i = 0; i < 4; i++)
                cp16(d + (uint32_t)TILE_BYTES + (uint32_t)(i * 32 * SPITCH * 2),
                     sB + (size_t)(i * 32) * KPAD);
        }
    };

    load_chunk(0, 0);
    asm volatile("cp.async.commit_group;");

    int buf = 0;
    for (int ch = 0; ch < NCHUNKS; ch++) {
        if (ch + 1 < NCHUNKS) {
            load_chunk(buf ^ 1, ch + 1);
            asm volatile("cp.async.commit_group;");
            asm volatile("cp.async.wait_group 1;");
        } else {
            asm volatile("cp.async.wait_group 0;");
        }
        __syncthreads();

        uint32_t aOff = aBase + (uint32_t)buf * BUF_BYTES;
        uint32_t bOff = bBase + (uint32_t)buf * BUF_BYTES;

#pragma unroll
        for (int kk = 0; kk < 4; kk++) {
            uint32_t ka = aOff + (uint32_t)kk * 32;
            uint32_t kb = bOff + (uint32_t)kk * 32;
            uint32_t afr[4][4];
#pragma unroll
            for (int mi = 0; mi < 4; mi++)
                ldsm4(afr[mi], ka + (uint32_t)(mi * 16 * SPITCH * 2));
            uint32_t bfr[2][4];
#pragma unroll
            for (int np = 0; np < 2; np++)
                ldsm4(bfr[np], kb + (uint32_t)(np * 16 * SPITCH * 2));
#pragma unroll
            for (int mi = 0; mi < 4; mi++)
#pragma unroll
                for (int ni = 0; ni < 4; ni++) {
                    uint32_t b0 = bfr[ni >> 1][(ni & 1) * 2 + 0];
                    uint32_t b1 = bfr[ni >> 1][(ni & 1) * 2 + 1];
                    asm volatile(
                        "mma.sync.aligned.m16n8k16.row.col.f32.f16.f16.f32 "
                        "{%0,%1,%2,%3}, {%4,%5,%6,%7}, {%8,%9}, {%0,%1,%2,%3};"
                        : "+f"(acc[mi][ni][0]), "+f"(acc[mi][ni][1]),
                          "+f"(acc[mi][ni][2]), "+f"(acc[mi][ni][3])
                        : "r"(afr[mi][0]), "r"(afr[mi][1]),
                          "r"(afr[mi][2]), "r"(afr[mi][3]),
                          "r"(b0), "r"(b1));
                }
        }
        __syncthreads();
        buf ^= 1;
    }

    // epilogue: D frag (m = lane>>2 (+8), n = (lane&3)*2 (+1))
    int c1b = tm * 128 + warp_m * 64;
    int c2b = tn * 128 + warp_n * 32;
    int r = lane >> 2, cc = (lane & 3) * 2;
#pragma unroll
    for (int mi = 0; mi < 4; mi++) {
#pragma unroll
        for (int ni = 0; ni < 4; ni++) {
            float* d0 = g_G + ((size_t)(b * INPUT_DIM + c1b + mi * 16 + r)) * INPUT_DIM
                        + c2b + ni * 8 + cc;
            *(float2*)d0 = make_float2(acc[mi][ni][0], acc[mi][ni][1]);
            float* d1 = d0 + 8 * INPUT_DIM;
            *(float2*)d1 = make_float2(acc[mi][ni][2], acc[mi][ni][3]);
        }
    }
}

// ---------------- kernel 5: transpose G (batch-major) -> T (batch-last) ------
__global__ void transpose_kernel() {
    __shared__ float sm[8 * 32 * 33];
    int c1b = blockIdx.y * 8;
    int c2b = blockIdx.x * 32;
    if (c1b > c2b + 31) return;
    int tid = threadIdx.x;
    int lane = tid & 31, w = tid >> 5;

#pragma unroll 4
    for (int i = 0; i < 32; i++) {
        int j = i * 8 + w;
        int b = j >> 3, c1i = j & 7;
        float v = g_G[((size_t)b * INPUT_DIM + (c1b + c1i)) * INPUT_DIM + c2b + lane];
        sm[(c1i * 32 + lane) * 33 + b] = v;
    }
    __syncthreads();
#pragma unroll 4
    for (int i = 0; i < 32; i++) {
        int j = i * 8 + w;
        int c1i = j >> 5, c2i = j & 31;
        float v = sm[(c1i * 32 + c2i) * 33 + lane];
        g_T[((size_t)(c1b + c1i) * INPUT_DIM + (c2b + c2i)) * BATCH + lane] = v;
    }
}

// ---------------- kernel 6: gather pairs per bin + norm reduce ----------------
__global__ void gather_kernel() {
    __shared__ float sums[8][33];
    int warp = threadIdx.x >> 5, lane = threadIdx.x & 31;
    int bin = blockIdx.x * 8 + warp;
    int cnt = min(g_cnt[bin], CAP);
    const int2* pl = g_pairs + bin * CAP;
    float acc = 0.0f;
    int i = 0;
    for (; i + 4 <= cnt; i += 4) {
        int2 p0 = pl[i + 0];
        int2 p1 = pl[i + 1];
        int2 p2 = pl[i + 2];
        int2 p3 = pl[i + 3];
        float v0 = g_T[p0.x + lane];
        float v1 = g_T[p1.x + lane];
        float v2 = g_T[p2.x + lane];
        float v3 = g_T[p3.x + lane];
        acc = fmaf(__int_as_float(p0.y), v0, acc);
        acc = fmaf(__int_as_float(p1.y), v1, acc);
        acc = fmaf(__int_as_float(p2.y), v2, acc);
        acc = fmaf(__int_as_float(p3.y), v3, acc);
    }
    for (; i < cnt; i++) {
        int2 p = pl[i];
        acc = fmaf(__int_as_float(p.y), g_T[p.x + lane], acc);
    }
    g_Y[bin * BATCH + lane] = acc;
    sums[warp][lane] = fabsf(acc);
    __syncthreads();
    if (warp == 0) {
        float s = 0.0f;
#pragma unroll
        for (int w = 0; w < 8; w++) s += sums[w][lane];
        atomicAdd(&g_norm[lane], s);
    }
}

// ---------------- kernel 7: signed sqrt + L2 normalize (parallel) -------------
__global__ void scale_kernel(float* __restrict__ out) {
    __shared__ float sm[32][33];
    int bin0 = blockIdx.x * 32;
    int lane = threadIdx.x & 31, w = threadIdx.x >> 5;   // 8 warps

#pragma unroll
    for (int r = w; r < 32; r += 8)
        sm[r][lane] = g_Y[(bin0 + r) * BATCH + lane];
    __syncthreads();

#pragma unroll
    for (int b = w; b < 32; b += 8) {
        float inv = rsqrtf(fmaxf(g_norm[b], 1e-10f));
        float v = sm[lane][b];
        out[(size_t)b * PROJ_DIM + bin0 + lane] = copysignf(sqrtf(fabsf(v)), v) * inv;
    }
}

// ---------------- launcher ---------------------------------------------------
extern "C" void kernel_launch(void* const* d_in, const int* in_sizes, int n_in,
                              void* d_out, int out_size) {
    const float* x  = (const float*)d_in[0];   // [32,14,14,512]
    const float* M1 = (const float*)d_in[1];   // [512,8192]
    const float* M2 = (const float*)d_in[2];   // [512,8192]
    float* out = (float*)d_out;                // [32,8192]
    (void)in_sizes; (void)n_in; (void)out_size;

    static cudaStream_t s1 = nullptr;
    static cudaEvent_t evFork = nullptr, evJoin = nullptr;
    static int init_done = 0;
    if (!init_done) {
        cudaStreamCreateWithFlags(&s1, cudaStreamNonBlocking);
        cudaEventCreateWithFlags(&evFork, cudaEventDisableTiming);
        cudaEventCreateWithFlags(&evJoin, cudaEventDisableTiming);
        cudaFuncSetAttribute(gram_hmma_kernel,
                             cudaFuncAttributeMaxDynamicSharedMemorySize,
                             2 * BUF_BYTES);
        init_done = 1;
    }

    void* cnt_addr; void* norm_addr;
    cudaGetSymbolAddress(&cnt_addr, g_cnt);
    cudaGetSymbolAddress(&norm_addr, g_norm);

    // fork: sketch path on s1, gram path on default stream
    cudaEventRecord(evFork, 0);
    cudaStreamWaitEvent(s1, evFork, 0);

    // --- branch B (s1): count-sketch CSR build ---
    cudaMemsetAsync(cnt_addr, 0, PROJ_DIM * sizeof(int), s1);
    extract_both_kernel<<<2 * INPUT_DIM, 256, 0, s1>>>(M1, M2);
    fill_kernel<<<NPAIRS / 1024, 256, 0, s1>>>();
    cudaEventRecord(evJoin, s1);

    // --- branch A (default): Gram path ---
    cudaMemsetAsync(norm_addr, 0, BATCH * sizeof(float));
    {
        dim3 grid(8, 4, BATCH);
        prep_split_kernel<<<grid, 256>>>(x);
    }
    {
        dim3 grid(10, BATCH);
        gram_hmma_kernel<<<grid, 256, 2 * BUF_BYTES>>>();
    }
    {
        dim3 grid(16, 64);
        transpose_kernel<<<grid, 256>>>();
    }

    // join, then gather + scale
    cudaStreamWaitEvent(0, evJoin, 0);
    gather_kernel<<<PROJ_DIM / 8, 256>>>();
    scale_kernel<<<PROJ_DIM / 32, 256>>>(out);
}

// round 13
// speedup vs baseline: 1.3235x; 1.3235x over previous
#include <cuda_runtime.h>
#include <cuda_fp16.h>
#include <math.h>
#include <stdint.h>

#define INPUT_DIM 512
#define PROJ_DIM  8192
#define HW        196
#define BATCH     32
#define NPAIRS    (INPUT_DIM * INPUT_DIM)
#define KPAD      448      // 2*196 = 392 padded to 7*64 (interleaved hi/lo fp16 splits)
#define KCHUNK    64
#define NCHUNKS   (KPAD / KCHUNK)
#define CAP       128      // bucket capacity (mean 32, Poisson tail ~0 at 128)

// ---------------- scratch (device globals; no allocation allowed) -----------
__device__ float          g_G[BATCH * INPUT_DIM * INPUT_DIM];  // Gram, batch-major (upper 128-tiles valid)
__device__ float          g_T[INPUT_DIM * INPUT_DIM * BATCH];  // Gram, batch-last
__device__ float          g_Y[PROJ_DIM * BATCH];               // pooled sketch, [bin][batch]
__device__ unsigned short g_xsp[BATCH * INPUT_DIM * KPAD];     // fp16 split-stacked x^T
__device__ int   g_h1[INPUT_DIM], g_h2[INPUT_DIM];
__device__ float g_s1[INPUT_DIM], g_s2[INPUT_DIM];
__device__ int   g_cnt[PROJ_DIM];                              // per-bin pair count
__device__ int2  g_pairs[PROJ_DIM * CAP];                      // {T-address, scale bits}
__device__ float g_norm[BATCH];                                // sum |Y| per batch

// ---------------- kernel 1: extract both count-sketches ----------------------
__global__ void extract_both_kernel(const float* __restrict__ M1,
                                    const float* __restrict__ M2) {
    int blk = blockIdx.x;
    const float* M; int* h; float* s; int row;
    if (blk < INPUT_DIM) { M = M1; h = g_h1; s = g_s1; row = blk; }
    else                 { M = M2; h = g_h2; s = g_s2; row = blk - INPUT_DIM; }
    const float* r = M + (size_t)row * PROJ_DIM;
    for (int j = threadIdx.x; j < PROJ_DIM; j += blockDim.x) {
        float v = r[j];
        if (v != 0.0f) { h[row] = j; s[row] = v; }
    }
}

// ---------------- kernel 2: fill buckets (single pass, no scan) ---------------
__global__ void fill_kernel() {
    int t = blockIdx.x * 256 + threadIdx.x;
    int c1  = t >> 7;
    int c2b = (t & 127) * 4;
    int   h1 = g_h1[c1];
    float s1 = g_s1[c1];
#pragma unroll
    for (int i = 0; i < 4; i++) {
        int c2 = c2b + i;
        int k = (h1 + g_h2[c2]) & (PROJ_DIM - 1);
        int pos = atomicAdd(&g_cnt[k], 1);
        if (pos < CAP) {
            int cmin = min(c1, c2), cmax = max(c1, c2);
            g_pairs[k * CAP + pos] =
                make_int2((cmin * INPUT_DIM + cmax) * BATCH,
                          __float_as_int(s1 * g_s2[c2]));
        }
    }
}

// ---------------- kernel 3: prep — fp16 split + transpose to [b][c][kk] -------
__global__ void prep_split_kernel(const float* __restrict__ x) {
    __shared__ float sm[64][65];
    int b = blockIdx.z, hwt = blockIdx.y, ct = blockIdx.x;
    int hw0 = hwt * 64, c0 = ct * 64;
    int t = threadIdx.x;

#pragma unroll
    for (int p = 0; p < 4; p++) {
        int row = p * 16 + (t >> 4);
        int col = (t & 15) * 4;
        int hw = hw0 + row;
        float4 v = make_float4(0.f, 0.f, 0.f, 0.f);
        if (hw < HW)
            v = *(const float4*)(x + ((size_t)(b * HW + hw)) * INPUT_DIM + c0 + col);
        sm[row][col] = v.x; sm[row][col + 1] = v.y;
        sm[row][col + 2] = v.z; sm[row][col + 3] = v.w;
    }
    __syncthreads();

    int c_i = t >> 2, q = t & 3;
    int kkbase = 2 * hw0 + q * 32;     // 32 kk = 16 hw
    if (kkbase < KPAD) {
        uint32_t outw[16];
#pragma unroll
        for (int i = 0; i < 16; i++) {
            int hwl = q * 16 + i;
            float v = (hw0 + hwl < HW) ? sm[hwl][c_i] : 0.0f;
            __half h1 = __float2half_rn(v);
            float r = v - __half2float(h1);
            __half h2 = __float2half_rn(r);
            outw[i] = ((uint32_t)__half_as_ushort(h2) << 16) |
                      (uint32_t)__half_as_ushort(h1);
        }
        uint4* dst = (uint4*)(g_xsp + ((size_t)(b * INPUT_DIM + c0 + c_i)) * KPAD + kkbase);
        const uint4* s = (const uint4*)outw;
        dst[0] = s[0]; dst[1] = s[1]; dst[2] = s[2]; dst[3] = s[3];
    }
}

// ---------------- kernel 4: HMMA fp16 Gram, ldmatrix + cp.async (occ-2) -------
#define SPITCH     72                     // fp16 elems per smem row (conflict-free)
#define TILE_ELEM  (128 * SPITCH)
#define TILE_BYTES (TILE_ELEM * 2)
#define BUF_ELEM   (2 * TILE_ELEM)        // A + B per buffer
#define BUF_BYTES  (BUF_ELEM * 2)

__device__ __forceinline__ void cp16(uint32_t dst, const void* src) {
    asm volatile("cp.async.cg.shared.global [%0], [%1], 16;" :: "r"(dst), "l"(src));
}
__device__ __forceinline__ void ldsm4(uint32_t* r, uint32_t a) {
    asm volatile("ldmatrix.sync.aligned.m8n8.x4.shared.b16 {%0,%1,%2,%3}, [%4];"
                 : "=r"(r[0]), "=r"(r[1]), "=r"(r[2]), "=r"(r[3]) : "r"(a));
}

__global__ __launch_bounds__(256) void gram_hmma_kernel() {
    extern __shared__ __align__(16) unsigned short smh[];
    uint32_t smemBase = (uint32_t)__cvta_generic_to_shared(smh);

    int b = blockIdx.y;
    int tt = blockIdx.x, tm = 0, rem = 4;
    while (tt >= rem) { tt -= rem; tm++; rem--; }
    int tn = tm + tt;
    bool diag = (tm == tn);

    int t = threadIdx.x, lane = t & 31, wid = t >> 5;
    int warp_m = wid & 1, warp_n = wid >> 1;

    float acc[4][4][4];
#pragma unroll
    for (int mi = 0; mi < 4; mi++)
#pragma unroll
        for (int ni = 0; ni < 4; ni++)
#pragma unroll
            for (int j = 0; j < 4; j++) acc[mi][ni][j] = 0.0f;

    const unsigned short* baseA = g_xsp + ((size_t)(b * INPUT_DIM + tm * 128)) * KPAD;
    const unsigned short* baseB = g_xsp + ((size_t)(b * INPUT_DIM + tn * 128)) * KPAD;

    // precomputed cp.async lane geometry
    int cprow = t >> 3, cpj = (t & 7) * 8;
    uint32_t cpDst = smemBase + (uint32_t)(cprow * SPITCH + cpj) * 2;
    const unsigned short* cpSrcA = baseA + (size_t)cprow * KPAD + cpj;
    const unsigned short* cpSrcB = baseB + (size_t)cprow * KPAD + cpj;

    // precomputed ldmatrix base addresses (bytes)
    int arow = (lane & 7) + ((lane >> 3) & 1) * 8;
    int acol = (lane >> 4) * 8;
    int brow = (lane & 7) + (lane >> 4) * 8;
    int bcol = ((lane >> 3) & 1) * 8;
    uint32_t aBase = smemBase + (uint32_t)((warp_m * 64 + arow) * SPITCH + acol) * 2;
    uint32_t bBase = smemBase + (uint32_t)((warp_n * 32 + brow) * SPITCH + bcol) * 2
                     + (diag ? 0u : (uint32_t)TILE_BYTES);

    auto load_chunk = [&](int buf, int ch) {
        uint32_t d = cpDst + (uint32_t)buf * BUF_BYTES;
        const unsigned short* sA = cpSrcA + ch * KCHUNK;
#pragma unroll
        for (int i = 0; i < 4; i++)
            cp16(d + (uint32_t)(i * 32 * SPITCH * 2), sA + (size_t)(i * 32) * KPAD);
        if (!diag) {
            const unsigned short* sB = cpSrcB + ch * KCHUNK;
#pragma unroll
            for (int i = 0; i < 4; i++)
                cp16(d + (uint32_t)TILE_BYTES + (uint32_t)(i * 32 * SPITCH * 2),
                     sB + (size_t)(i * 32) * KPAD);
        }
    };

    load_chunk(0, 0);
    asm volatile("cp.async.commit_group;");

    int buf = 0;
    for (int ch = 0; ch < NCHUNKS; ch++) {
        if (ch + 1 < NCHUNKS) {
            load_chunk(buf ^ 1, ch + 1);
            asm volatile("cp.async.commit_group;");
            asm volatile("cp.async.wait_group 1;");
        } else {
            asm volatile("cp.async.wait_group 0;");
        }
        __syncthreads();

        uint32_t aOff = aBase + (uint32_t)buf * BUF_BYTES;
        uint32_t bOff = bBase + (uint32_t)buf * BUF_BYTES;

#pragma unroll
        for (int kk = 0; kk < 4; kk++) {
            uint32_t ka = aOff + (uint32_t)kk * 32;
            uint32_t kb = bOff + (uint32_t)kk * 32;
            uint32_t afr[4][4];
#pragma unroll
            for (int mi = 0; mi < 4; mi++)
                ldsm4(afr[mi], ka + (uint32_t)(mi * 16 * SPITCH * 2));
            uint32_t bfr[2][4];
#pragma unroll
            for (int np = 0; np < 2; np++)
                ldsm4(bfr[np], kb + (uint32_t)(np * 16 * SPITCH * 2));
#pragma unroll
            for (int mi = 0; mi < 4; mi++)
#pragma unroll
                for (int ni = 0; ni < 4; ni++) {
                    uint32_t b0 = bfr[ni >> 1][(ni & 1) * 2 + 0];
                    uint32_t b1 = bfr[ni >> 1][(ni & 1) * 2 + 1];
                    asm volatile(
                        "mma.sync.aligned.m16n8k16.row.col.f32.f16.f16.f32 "
                        "{%0,%1,%2,%3}, {%4,%5,%6,%7}, {%8,%9}, {%0,%1,%2,%3};"
                        : "+f"(acc[mi][ni][0]), "+f"(acc[mi][ni][1]),
                          "+f"(acc[mi][ni][2]), "+f"(acc[mi][ni][3])
                        : "r"(afr[mi][0]), "r"(afr[mi][1]),
                          "r"(afr[mi][2]), "r"(afr[mi][3]),
                          "r"(b0), "r"(b1));
                }
        }
        __syncthreads();
        buf ^= 1;
    }

    // epilogue: D frag (m = lane>>2 (+8), n = (lane&3)*2 (+1))
    int c1b = tm * 128 + warp_m * 64;
    int c2b = tn * 128 + warp_n * 32;
    int r = lane >> 2, cc = (lane & 3) * 2;
#pragma unroll
    for (int mi = 0; mi < 4; mi++) {
#pragma unroll
        for (int ni = 0; ni < 4; ni++) {
            float* d0 = g_G + ((size_t)(b * INPUT_DIM + c1b + mi * 16 + r)) * INPUT_DIM
                        + c2b + ni * 8 + cc;
            *(float2*)d0 = make_float2(acc[mi][ni][0], acc[mi][ni][1]);
            float* d1 = d0 + 8 * INPUT_DIM;
            *(float2*)d1 = make_float2(acc[mi][ni][2], acc[mi][ni][3]);
        }
    }
}

// ---------------- kernel 5: transpose G (batch-major) -> T (batch-last) ------
__global__ void transpose_kernel() {
    __shared__ float sm[8 * 32 * 33];
    int c1b = blockIdx.y * 8;
    int c2b = blockIdx.x * 32;
    if (c1b > c2b + 31) return;
    int tid = threadIdx.x;
    int lane = tid & 31, w = tid >> 5;

#pragma unroll 4
    for (int i = 0; i < 32; i++) {
        int j = i * 8 + w;
        int b = j >> 3, c1i = j & 7;
        float v = g_G[((size_t)b * INPUT_DIM + (c1b + c1i)) * INPUT_DIM + c2b + lane];
        sm[(c1i * 32 + lane) * 33 + b] = v;
    }
    __syncthreads();
#pragma unroll 4
    for (int i = 0; i < 32; i++) {
        int j = i * 8 + w;
        int c1i = j >> 5, c2i = j & 31;
        float v = sm[(c1i * 32 + c2i) * 33 + lane];
        g_T[((size_t)(c1b + c1i) * INPUT_DIM + (c2b + c2i)) * BATCH + lane] = v;
    }
}

// ---------------- kernel 6: gather pairs per bin + norm reduce ----------------
__global__ void gather_kernel() {
    __shared__ float sums[8][33];
    int warp = threadIdx.x >> 5, lane = threadIdx.x & 31;
    int bin = blockIdx.x * 8 + warp;
    int cnt = min(g_cnt[bin], CAP);
    const int2* pl = g_pairs + bin * CAP;
    float acc = 0.0f;
    int i = 0;
    for (; i + 4 <= cnt; i += 4) {
        int2 p0 = pl[i + 0];
        int2 p1 = pl[i + 1];
        int2 p2 = pl[i + 2];
        int2 p3 = pl[i + 3];
        float v0 = g_T[p0.x + lane];
        float v1 = g_T[p1.x + lane];
        float v2 = g_T[p2.x + lane];
        float v3 = g_T[p3.x + lane];
        acc = fmaf(__int_as_float(p0.y), v0, acc);
        acc = fmaf(__int_as_float(p1.y), v1, acc);
        acc = fmaf(__int_as_float(p2.y), v2, acc);
        acc = fmaf(__int_as_float(p3.y), v3, acc);
    }
    for (; i < cnt; i++) {
        int2 p = pl[i];
        acc = fmaf(__int_as_float(p.y), g_T[p.x + lane], acc);
    }
    g_Y[bin * BATCH + lane] = acc;
    sums[warp][lane] = fabsf(acc);
    __syncthreads();
    if (warp == 0) {
        float s = 0.0f;
#pragma unroll
        for (int w = 0; w < 8; w++) s += sums[w][lane];
        atomicAdd(&g_norm[lane], s);
    }
}

// ---------------- kernel 7: signed sqrt + L2 normalize (parallel) -------------
__global__ void scale_kernel(float* __restrict__ out) {
    __shared__ float sm[32][33];
    int bin0 = blockIdx.x * 32;
    int lane = threadIdx.x & 31, w = threadIdx.x >> 5;   // 8 warps

#pragma unroll
    for (int r = w; r < 32; r += 8)
        sm[r][lane] = g_Y[(bin0 + r) * BATCH + lane];
    __syncthreads();

#pragma unroll
    for (int b = w; b < 32; b += 8) {
        float inv = rsqrtf(fmaxf(g_norm[b], 1e-10f));
        float v = sm[lane][b];
        out[(size_t)b * PROJ_DIM + bin0 + lane] = copysignf(sqrtf(fabsf(v)), v) * inv;
    }
}

// ---------------- launcher ---------------------------------------------------
extern "C" void kernel_launch(void* const* d_in, const int* in_sizes, int n_in,
                              void* d_out, int out_size) {
    const float* x  = (const float*)d_in[0];   // [32,14,14,512]
    const float* M1 = (const float*)d_in[1];   // [512,8192]
    const float* M2 = (const float*)d_in[2];   // [512,8192]
    float* out = (float*)d_out;                // [32,8192]
    (void)in_sizes; (void)n_in; (void)out_size;

    static cudaStream_t s1 = nullptr;
    static cudaEvent_t evFork = nullptr, evJoin = nullptr;
    static int init_done = 0;
    if (!init_done) {
        cudaStreamCreateWithFlags(&s1, cudaStreamNonBlocking);
        cudaEventCreateWithFlags(&evFork, cudaEventDisableTiming);
        cudaEventCreateWithFlags(&evJoin, cudaEventDisableTiming);
        cudaFuncSetAttribute(gram_hmma_kernel,
                             cudaFuncAttributeMaxDynamicSharedMemorySize,
                             2 * BUF_BYTES);
        init_done = 1;
    }

    void* cnt_addr; void* norm_addr;
    cudaGetSymbolAddress(&cnt_addr, g_cnt);
    cudaGetSymbolAddress(&norm_addr, g_norm);

    // fork: sketch path on s1, gram path on default stream
    cudaEventRecord(evFork, 0);
    cudaStreamWaitEvent(s1, evFork, 0);

    // --- branch B (s1): count-sketch bucket build + norm zero ---
    cudaMemsetAsync(cnt_addr, 0, PROJ_DIM * sizeof(int), s1);
    cudaMemsetAsync(norm_addr, 0, BATCH * sizeof(float), s1);
    extract_both_kernel<<<2 * INPUT_DIM, 256, 0, s1>>>(M1, M2);
    fill_kernel<<<NPAIRS / 1024, 256, 0, s1>>>();
    cudaEventRecord(evJoin, s1);

    // --- branch A (default): Gram path ---
    {
        dim3 grid(8, 4, BATCH);
        prep_split_kernel<<<grid, 256>>>(x);
    }
    {
        dim3 grid(10, BATCH);
        gram_hmma_kernel<<<grid, 256, 2 * BUF_BYTES>>>();
    }
    {
        dim3 grid(16, 64);
        transpose_kernel<<<grid, 256>>>();
    }

    // join, then gather + scale
    cudaStreamWaitEvent(0, evJoin, 0);
    gather_kernel<<<PROJ_DIM / 8, 256>>>();
    scale_kernel<<<PROJ_DIM / 32, 256>>>(out);
}